// round 3
// baseline (speedup 1.0000x reference)
#include <cuda_runtime.h>
#include <cstdint>
#include <cstddef>

#define NTHREADS 512
#define TBATCH   16
#define FEAT     832            // 64 * (1+3+9)
#define NPATH    15
#define WSZ      262144         // 64*64*64 weights per path

// Path tables: (L1, L2, Lout) in PATHS enumeration order.
__constant__ int c_L1[NPATH] = {0,0,0,1,1,1,1,1,1,2,2,2,2,2,2};
__constant__ int c_L2[NPATH] = {0,1,2,0,1,1,1,2,2,0,1,1,2,2,2};
__constant__ int c_LO[NPATH] = {0,1,2,1,2,0,1,1,2,2,1,2,2,0,1};

// Packed dual-fp32 FMA (FFMA2): only reachable via PTX fma.rn.f32x2.
__device__ __forceinline__ void ffma2(unsigned long long &d, unsigned long long a, unsigned long long b) {
    asm("fma.rn.f32x2 %0, %1, %2, %0;" : "+l"(d) : "l"(a), "l"(b));
}
__device__ __forceinline__ unsigned long long packf2(float x, float y) {
    unsigned long long r; asm("mov.b64 %0, {%1,%2};" : "=l"(r) : "f"(x), "f"(y)); return r;
}
__device__ __forceinline__ void unpackf2(unsigned long long v, float &x, float &y) {
    asm("mov.b64 {%0,%1}, %2;" : "=f"(x), "=f"(y) : "l"(v));
}

// smem layout (floats): A tile | B tile | W stage (64x65 pad) | P stage (16*64*10)
#define SMEM_FLOATS (TBATCH*FEAT*2 + 64*65 + TBATCH*64*10)
#define SMEM_BYTES  (SMEM_FLOATS * 4)

__global__ void __launch_bounds__(NTHREADS, 1)
tp_kernel(const float* __restrict__ x1, const float* __restrict__ x2,
          const float* __restrict__ wgt, float* __restrict__ out)
{
    extern __shared__ float sm[];
    float* As = sm;                       // [TBATCH][832]
    float* Bs = As + TBATCH*FEAT;         // [TBATCH][832]
    float* Ws = Bs + TBATCH*FEAT;         // [64][65]   (c-major, pad 65)
    float* Ps = Ws + 64*65;               // [TBATCH*64][10]

    const int tid = threadIdx.x;
    const int w   = tid >> 5;             // warp id == batch index within tile
    const int l   = tid & 31;             // lane; owns c = l and c = l+32
    const int blk = blockIdx.x;

    // ---- load A/B tiles (flat, contiguous, float4) ----
    {
        const float4* g1 = (const float4*)(x1 + (size_t)blk * TBATCH * FEAT);
        const float4* g2 = (const float4*)(x2 + (size_t)blk * TBATCH * FEAT);
        float4* s1 = (float4*)As;
        float4* s2 = (float4*)Bs;
        const int nv = TBATCH*FEAT/4;     // 3328
        for (int idx = tid; idx < nv; idx += NTHREADS) { s1[idx] = g1[idx]; s2[idx] = g2[idx]; }
    }

    // ---- persistent accumulators: 2 channels x {L0(1), L1(3), L2(9)} ----
    float acc0[2] = {0.f, 0.f};
    unsigned long long a1p[2] = {0ull, 0ull};
    float a1s[2] = {0.f, 0.f};
    unsigned long long a2p[2][4] = {{0ull,0ull,0ull,0ull},{0ull,0ull,0ull,0ull}};
    float a2s[2] = {0.f, 0.f};

    // ---- W staging geometry: each thread owns 8 consecutive b's of one c row ----
    const int wc = tid >> 3;              // c row (0..63)
    const int wb = (tid & 7) * 8;         // b start (0,8,...,56)
    const float* wgbase = wgt + (size_t)wc * 4096 + wb;

    // prefetch first W chunk (p=0, a=0)
    float4 pf0, pf1;
    { const float4* g = (const float4*)wgbase; pf0 = g[0]; pf1 = g[1]; }

    #pragma unroll 1
    for (int p = 0; p < NPATH; ++p) {
        const int L1 = c_L1[p], L2 = c_L2[p], LO = c_LO[p];
        #pragma unroll 1
        for (int a = 0; a < 64; ++a) {
            __syncthreads();   // previous FMA phase done; also orders tile load on iter 0

            // store prefetched W chunk into smem
            {
                float* ws = Ws + wc*65 + wb;
                ws[0]=pf0.x; ws[1]=pf0.y; ws[2]=pf0.z; ws[3]=pf0.w;
                ws[4]=pf1.x; ws[5]=pf1.y; ws[6]=pf1.z; ws[7]=pf1.w;
            }

            // ---- pair-feature phase: P[tb*64+b][m] for this (p, a) ----
            const int aoff = (L1==0) ? a : ((L1==1) ? (64 + a*3) : (256 + a*9));
            #pragma unroll
            for (int it = 0; it < 2; ++it) {
                const int pr = tid + it*NTHREADS;        // 0..1023
                const int tb = pr >> 6, b = pr & 63;
                const float* Aa = As + tb*FEAT + aoff;
                const float* Bv = Bs + tb*FEAT + ((L2==0) ? b : ((L2==1) ? (64 + b*3) : (256 + b*9)));
                float* P = Ps + pr*10;
                switch (p) {
                case 0:  P[0] = Aa[0]*Bv[0]; break;
                case 1:  { float s=Aa[0]; P[0]=s*Bv[0]; P[1]=s*Bv[1]; P[2]=s*Bv[2]; } break;
                case 2:  {
                           float s=Aa[0];
                           #pragma unroll
                           for (int j=0;j<9;++j) P[j]=s*Bv[j];
                         } break;
                case 3:  { float s=Bv[0]; P[0]=Aa[0]*s; P[1]=Aa[1]*s; P[2]=Aa[2]*s; } break;
                case 4:  { float u0=Aa[0],u1=Aa[1],u2=Aa[2],v0=Bv[0],v1=Bv[1],v2=Bv[2];
                           P[0]=u0*v0;P[1]=u0*v1;P[2]=u0*v2;
                           P[3]=u1*v0;P[4]=u1*v1;P[5]=u1*v2;
                           P[6]=u2*v0;P[7]=u2*v1;P[8]=u2*v2; } break;
                case 5:  P[0] = Aa[0]*Bv[0] + Aa[1]*Bv[1] + Aa[2]*Bv[2]; break;
                case 6:  { float u0=Aa[0],u1=Aa[1],u2=Aa[2],v0=Bv[0],v1=Bv[1],v2=Bv[2];
                           P[0]=u1*v2-u2*v1; P[1]=u2*v0-u0*v2; P[2]=u0*v1-u1*v0; } break;
                case 7:  { float u0=Aa[0],u1=Aa[1],u2=Aa[2];
                           P[0]=u0*Bv[0]+u1*Bv[1]+u2*Bv[2];
                           P[1]=u0*Bv[3]+u1*Bv[4]+u2*Bv[5];
                           P[2]=u0*Bv[6]+u1*Bv[7]+u2*Bv[8]; } break;
                case 8:  {
                           float u0=Aa[0],u1=Aa[1],u2=Aa[2];
                           #pragma unroll
                           for (int e=0;e<3;++e) {
                               float v0=Bv[e*3],v1=Bv[e*3+1],v2=Bv[e*3+2];
                               P[e*3+0]=u1*v2-u2*v1; P[e*3+1]=u2*v0-u0*v2; P[e*3+2]=u0*v1-u1*v0;
                           }
                         } break;
                case 9:  {
                           float s=Bv[0];
                           #pragma unroll
                           for (int j=0;j<9;++j) P[j]=Aa[j]*s;
                         } break;
                case 10: { float v0=Bv[0],v1=Bv[1],v2=Bv[2];
                           P[0]=Aa[0]*v0+Aa[1]*v1+Aa[2]*v2;
                           P[1]=Aa[3]*v0+Aa[4]*v1+Aa[5]*v2;
                           P[2]=Aa[6]*v0+Aa[7]*v1+Aa[8]*v2; } break;
                case 11: {
                           float v0=Bv[0],v1=Bv[1],v2=Bv[2];
                           #pragma unroll
                           for (int d=0;d<3;++d) {
                               float u0=Aa[d*3],u1=Aa[d*3+1],u2=Aa[d*3+2];
                               P[d*3+0]=u1*v2-u2*v1; P[d*3+1]=u2*v0-u0*v2; P[d*3+2]=u0*v1-u1*v0;
                           }
                         } break;
                case 12: {
                           #pragma unroll
                           for (int d=0;d<3;++d) {
                               float u0=Aa[d*3],u1=Aa[d*3+1],u2=Aa[d*3+2];
                               #pragma unroll
                               for (int f=0;f<3;++f)
                                   P[d*3+f]=u0*Bv[f*3]+u1*Bv[f*3+1]+u2*Bv[f*3+2];
                           }
                         } break;
                case 13: {
                           float s=0.f;
                           #pragma unroll
                           for (int j=0;j<9;++j) s += Aa[j]*Bv[j];
                           P[0]=s;
                         } break;
                default: { // case 14: antisymmetric part of M[d][f] = dot(A2[d,:], B2[f,:])
                           float M01 = Aa[0]*Bv[3]+Aa[1]*Bv[4]+Aa[2]*Bv[5];
                           float M02 = Aa[0]*Bv[6]+Aa[1]*Bv[7]+Aa[2]*Bv[8];
                           float M10 = Aa[3]*Bv[0]+Aa[4]*Bv[1]+Aa[5]*Bv[2];
                           float M12 = Aa[3]*Bv[6]+Aa[4]*Bv[7]+Aa[5]*Bv[8];
                           float M20 = Aa[6]*Bv[0]+Aa[7]*Bv[1]+Aa[8]*Bv[2];
                           float M21 = Aa[6]*Bv[3]+Aa[7]*Bv[4]+Aa[8]*Bv[5];
                           P[0]=M12-M21; P[1]=M20-M02; P[2]=M01-M10; } break;
                }
            }

            // prefetch next step's W chunk (hidden under FMA phase)
            {
                int an = a + 1, pn = p;
                if (an == 64) { an = 0; pn = p + 1; }
                if (pn < NPATH) {
                    const float4* g = (const float4*)(wgbase + (size_t)pn*WSZ + an*64);
                    pf0 = g[0]; pf1 = g[1];
                }
            }

            __syncthreads();

            // ---- accumulate phase: this warp handles batch element `w` ----
            const float* Pw = Ps + w*640;            // (w*64 + b)*10
            if (LO == 2) {
                #pragma unroll 2
                for (int b = 0; b < 64; ++b) {
                    const float* pp = Pw + b*10;
                    unsigned long long p01 = *(const unsigned long long*)(pp);
                    unsigned long long p23 = *(const unsigned long long*)(pp+2);
                    unsigned long long p45 = *(const unsigned long long*)(pp+4);
                    unsigned long long p67 = *(const unsigned long long*)(pp+6);
                    float p8 = pp[8];
                    #pragma unroll
                    for (int i = 0; i < 2; ++i) {
                        float wv = Ws[(l + 32*i)*65 + b];
                        unsigned long long ww = packf2(wv, wv);
                        ffma2(a2p[i][0], ww, p01);
                        ffma2(a2p[i][1], ww, p23);
                        ffma2(a2p[i][2], ww, p45);
                        ffma2(a2p[i][3], ww, p67);
                        a2s[i] = fmaf(wv, p8, a2s[i]);
                    }
                }
            } else if (LO == 1) {
                #pragma unroll 4
                for (int b = 0; b < 64; ++b) {
                    const float* pp = Pw + b*10;
                    unsigned long long p01 = *(const unsigned long long*)(pp);
                    float p2 = pp[2];
                    #pragma unroll
                    for (int i = 0; i < 2; ++i) {
                        float wv = Ws[(l + 32*i)*65 + b];
                        unsigned long long ww = packf2(wv, wv);
                        ffma2(a1p[i], ww, p01);
                        a1s[i] = fmaf(wv, p2, a1s[i]);
                    }
                }
            } else {
                #pragma unroll 4
                for (int b = 0; b < 64; ++b) {
                    float p0 = Pw[b*10];
                    #pragma unroll
                    for (int i = 0; i < 2; ++i)
                        acc0[i] = fmaf(Ws[(l + 32*i)*65 + b], p0, acc0[i]);
                }
            }
        }
    }

    // ---- epilogue: write out[bidx, :] — every slot written exactly once ----
    float* o = out + ((size_t)blk*TBATCH + w) * FEAT;
    #pragma unroll
    for (int i = 0; i < 2; ++i) {
        const int c = l + 32*i;
        o[c] = acc0[i];
        float t0, t1;
        unpackf2(a1p[i], t0, t1);
        o[64 + c*3 + 0] = t0; o[64 + c*3 + 1] = t1; o[64 + c*3 + 2] = a1s[i];
        float* o2 = o + 256 + c*9;
        unpackf2(a2p[i][0], t0, t1); o2[0]=t0; o2[1]=t1;
        unpackf2(a2p[i][1], t0, t1); o2[2]=t0; o2[3]=t1;
        unpackf2(a2p[i][2], t0, t1); o2[4]=t0; o2[5]=t1;
        unpackf2(a2p[i][3], t0, t1); o2[6]=t0; o2[7]=t1;
        o2[8] = a2s[i];
    }
}

extern "C" void kernel_launch(void* const* d_in, const int* in_sizes, int n_in,
                              void* d_out, int out_size)
{
    const float* x1  = (const float*)d_in[0];
    const float* x2  = (const float*)d_in[1];
    const float* wgt = (const float*)d_in[2];
    float* out = (float*)d_out;

    const int nbatch = in_sizes[0] / FEAT;       // 4096
    const int grid   = nbatch / TBATCH;          // 256

    cudaFuncSetAttribute(tp_kernel, cudaFuncAttributeMaxDynamicSharedMemorySize, SMEM_BYTES);
    tp_kernel<<<grid, NTHREADS, SMEM_BYTES>>>(x1, x2, wgt, out);
}

// round 4
// speedup vs baseline: 1.6844x; 1.6844x over previous
#include <cuda_runtime.h>
#include <cstdint>
#include <cstddef>

#define FEAT     832            // 64 * (1+3+9)
#define NPATH    15
#define WSZ      262144         // 64*64*64 weights per path
#define NSTEPS   (NPATH*64)     // 960
#define TB       8              // batch elems per CTA
#define NT       128            // threads per CTA (4 warps; warp = 2 elems)
#define PROW     12             // floats per P row (9 used + pad, 16B aligned)
#define PESTRIDE 772            // 64*PROW + 4 (bank-offsets the two half-warp reads)
#define WBUF     4096           // floats per W step buffer (64 b x 64 c)

__constant__ int c_L1[NPATH] = {0,0,0,1,1,1,1,1,1,2,2,2,2,2,2};
__constant__ int c_L2[NPATH] = {0,1,2,0,1,1,1,2,2,0,1,1,2,2,2};
__constant__ int c_LO[NPATH] = {0,1,2,1,2,0,1,1,2,2,1,2,2,0,1};

// Transposed weights: g_wt[(p*64 + a)*4096 + b*64 + c]
__device__ float g_wt[NPATH * WSZ];

typedef unsigned long long ull;

__device__ __forceinline__ void ffma2(ull &d, ull a, ull b) {
    asm("fma.rn.f32x2 %0, %1, %2, %0;" : "+l"(d) : "l"(a), "l"(b));
}
__device__ __forceinline__ ull packf2(float x, float y) {
    ull r; asm("mov.b64 %0, {%1,%2};" : "=l"(r) : "f"(x), "f"(y)); return r;
}
__device__ __forceinline__ void unpackf2(ull v, float &x, float &y) {
    asm("mov.b64 {%0,%1}, %2;" : "=f"(x), "=f"(y) : "l"(v));
}
__device__ __forceinline__ uint32_t smem_u32(const void* p) {
    uint32_t a;
    asm("{ .reg .u64 t; cvta.to.shared.u64 t, %1; cvt.u32.u64 %0, t; }" : "=r"(a) : "l"(p));
    return a;
}
__device__ __forceinline__ void cpasync16(uint32_t dst, const void* src) {
    asm volatile("cp.async.cg.shared.global [%0], [%1], 16;" :: "r"(dst), "l"(src));
}

// ---------------- transpose kernel: wgt[p][c][a*64+b] -> g_wt[(p*64+a)][b][c] ----
__global__ void __launch_bounds__(256)
tp_transpose(const float* __restrict__ wgt)
{
    __shared__ float t[64*65];
    const int pa = blockIdx.x;              // 0..959
    const int p = pa >> 6, a = pa & 63;
    const float* src = wgt + (size_t)p*WSZ + (size_t)a*64;
    float* dst = g_wt + (size_t)pa*WBUF;
    const int tid = threadIdx.x;
    const int c = tid >> 2, bq = tid & 3;   // c 0..63, 16 b's per thread
    #pragma unroll
    for (int k = 0; k < 4; ++k) {
        float4 v = *(const float4*)(src + (size_t)c*4096 + bq*16 + k*4);
        int b = bq*16 + k*4;
        t[c*65+b] = v.x; t[c*65+b+1] = v.y; t[c*65+b+2] = v.z; t[c*65+b+3] = v.w;
    }
    __syncthreads();
    const int b2 = tid >> 2, cq = tid & 3;
    #pragma unroll
    for (int k = 0; k < 4; ++k) {
        int c0 = cq*16 + k*4;
        float4 v = make_float4(t[(c0+0)*65 + b2], t[(c0+1)*65 + b2],
                               t[(c0+2)*65 + b2], t[(c0+3)*65 + b2]);
        *(float4*)(dst + b2*64 + c0) = v;
    }
}

// ---------------- main kernel --------------------------------------------------
// smem floats: As 8*832 | Bs 8*832 | W 2*4096 | P 8*772  = 27680 floats (110.7KB)
#define SMEM_FLOATS (2*TB*FEAT + 2*WBUF + TB*PESTRIDE)
#define SMEM_BYTES  (SMEM_FLOATS*4)

__global__ void __launch_bounds__(NT, 2)
tp_main(const float* __restrict__ x1, const float* __restrict__ x2,
        float* __restrict__ out)
{
    extern __shared__ float sm[];
    float* As = sm;                       // [TB][832]
    float* Bs = As + TB*FEAT;
    float* Wb = Bs + TB*FEAT;             // 2 x [64 b][64 c]
    float* Ps = Wb + 2*WBUF;              // [TB][PESTRIDE]

    const int tid = threadIdx.x;
    const int w   = tid >> 5;             // warp 0..3
    const int l   = tid & 31;
    const int h   = l >> 4;               // half-warp = which elem
    const int cl  = l & 15;               // owns channels 4cl..4cl+3
    const int e   = 2*w + h;              // elem within tile (0..7)
    const int blk = blockIdx.x;

    // ---- tile load ----
    {
        const float4* g1 = (const float4*)(x1 + (size_t)blk*TB*FEAT);
        const float4* g2 = (const float4*)(x2 + (size_t)blk*TB*FEAT);
        float4* s1 = (float4*)As; float4* s2 = (float4*)Bs;
        const int nv = TB*FEAT/4;         // 1664
        for (int i = tid; i < nv; i += NT) { s1[i] = g1[i]; s2[i] = g2[i]; }
    }

    // ---- accumulators: 4 channels x {1,3,9} ----
    float acc0[4] = {0,0,0,0};
    ull   a1p[4] = {0,0,0,0};
    float a1s[4] = {0,0,0,0};
    ull   a2p[4][4] = {{0,0,0,0},{0,0,0,0},{0,0,0,0},{0,0,0,0}};
    float a2s[4] = {0,0,0,0};

    // ---- W copy machinery (each thread copies 128B = 8 x 16B) ----
    const uint32_t wsm0 = smem_u32(Wb) + tid*128;
    const float* wtsrc0 = g_wt + (size_t)tid*32;

    // issue copy for step 0 into buffer 0
    {
        const float* s = wtsrc0;
        #pragma unroll
        for (int k = 0; k < 8; ++k) cpasync16(wsm0 + k*16, s + k*4);
        asm volatile("cp.async.commit_group;");
    }
    __syncthreads();   // tile load visible before pair phase

    int p = 0, a = 0;
    #pragma unroll 1
    for (int s = 0; s < NSTEPS; ++s) {
        // prefetch next step's W into the other buffer
        if (s + 1 < NSTEPS) {
            const float* src = wtsrc0 + (size_t)(s+1)*WBUF;
            const uint32_t dst = wsm0 + ((s+1)&1)*(WBUF*4);
            #pragma unroll
            for (int k = 0; k < 8; ++k) cpasync16(dst + k*16, src + k*4);
        }
        asm volatile("cp.async.commit_group;");

        const int L1 = c_L1[p], L2 = c_L2[p], LO = c_LO[p];
        const int aoff = (L1==0) ? a : ((L1==1) ? (64 + a*3) : (256 + a*9));

        // ---- pair phase: 512 rows / 128 threads = 4 rows each ----
        #pragma unroll
        for (int it = 0; it < 4; ++it) {
            const int pr = tid + it*NT;               // 0..511
            const int tb = pr >> 6, b = pr & 63;
            const float* Aa = As + tb*FEAT + aoff;
            const float* Bv = Bs + tb*FEAT + ((L2==0) ? b : ((L2==1) ? (64 + b*3) : (256 + b*9)));
            float* Pdst = Ps + tb*PESTRIDE + b*PROW;
            float P[9];
            switch (p) {
            case 0:  P[0] = Aa[0]*Bv[0]; break;
            case 1:  { float v=Aa[0]; P[0]=v*Bv[0]; P[1]=v*Bv[1]; P[2]=v*Bv[2]; } break;
            case 2:  {
                       float v=Aa[0];
                       #pragma unroll
                       for (int j=0;j<9;++j) P[j]=v*Bv[j];
                     } break;
            case 3:  { float v=Bv[0]; P[0]=Aa[0]*v; P[1]=Aa[1]*v; P[2]=Aa[2]*v; } break;
            case 4:  { float u0=Aa[0],u1=Aa[1],u2=Aa[2],v0=Bv[0],v1=Bv[1],v2=Bv[2];
                       P[0]=u0*v0;P[1]=u0*v1;P[2]=u0*v2;
                       P[3]=u1*v0;P[4]=u1*v1;P[5]=u1*v2;
                       P[6]=u2*v0;P[7]=u2*v1;P[8]=u2*v2; } break;
            case 5:  P[0] = Aa[0]*Bv[0] + Aa[1]*Bv[1] + Aa[2]*Bv[2]; break;
            case 6:  { float u0=Aa[0],u1=Aa[1],u2=Aa[2],v0=Bv[0],v1=Bv[1],v2=Bv[2];
                       P[0]=u1*v2-u2*v1; P[1]=u2*v0-u0*v2; P[2]=u0*v1-u1*v0; } break;
            case 7:  { float u0=Aa[0],u1=Aa[1],u2=Aa[2];
                       P[0]=u0*Bv[0]+u1*Bv[1]+u2*Bv[2];
                       P[1]=u0*Bv[3]+u1*Bv[4]+u2*Bv[5];
                       P[2]=u0*Bv[6]+u1*Bv[7]+u2*Bv[8]; } break;
            case 8:  {
                       float u0=Aa[0],u1=Aa[1],u2=Aa[2];
                       #pragma unroll
                       for (int q=0;q<3;++q) {
                           float v0=Bv[q*3],v1=Bv[q*3+1],v2=Bv[q*3+2];
                           P[q*3+0]=u1*v2-u2*v1; P[q*3+1]=u2*v0-u0*v2; P[q*3+2]=u0*v1-u1*v0;
                       }
                     } break;
            case 9:  {
                       float v=Bv[0];
                       #pragma unroll
                       for (int j=0;j<9;++j) P[j]=Aa[j]*v;
                     } break;
            case 10: { float v0=Bv[0],v1=Bv[1],v2=Bv[2];
                       P[0]=Aa[0]*v0+Aa[1]*v1+Aa[2]*v2;
                       P[1]=Aa[3]*v0+Aa[4]*v1+Aa[5]*v2;
                       P[2]=Aa[6]*v0+Aa[7]*v1+Aa[8]*v2; } break;
            case 11: {
                       float v0=Bv[0],v1=Bv[1],v2=Bv[2];
                       #pragma unroll
                       for (int d=0;d<3;++d) {
                           float u0=Aa[d*3],u1=Aa[d*3+1],u2=Aa[d*3+2];
                           P[d*3+0]=u1*v2-u2*v1; P[d*3+1]=u2*v0-u0*v2; P[d*3+2]=u0*v1-u1*v0;
                       }
                     } break;
            case 12: {
                       #pragma unroll
                       for (int d=0;d<3;++d) {
                           float u0=Aa[d*3],u1=Aa[d*3+1],u2=Aa[d*3+2];
                           #pragma unroll
                           for (int f=0;f<3;++f)
                               P[d*3+f]=u0*Bv[f*3]+u1*Bv[f*3+1]+u2*Bv[f*3+2];
                       }
                     } break;
            case 13: {
                       float v=0.f;
                       #pragma unroll
                       for (int j=0;j<9;++j) v += Aa[j]*Bv[j];
                       P[0]=v;
                     } break;
            default: { // 14: antisymmetric part of M[d][f] = dot(A2[d,:], B2[f,:])
                       float M01 = Aa[0]*Bv[3]+Aa[1]*Bv[4]+Aa[2]*Bv[5];
                       float M02 = Aa[0]*Bv[6]+Aa[1]*Bv[7]+Aa[2]*Bv[8];
                       float M10 = Aa[3]*Bv[0]+Aa[4]*Bv[1]+Aa[5]*Bv[2];
                       float M12 = Aa[3]*Bv[6]+Aa[4]*Bv[7]+Aa[5]*Bv[8];
                       float M20 = Aa[6]*Bv[0]+Aa[7]*Bv[1]+Aa[8]*Bv[2];
                       float M21 = Aa[6]*Bv[3]+Aa[7]*Bv[4]+Aa[8]*Bv[5];
                       P[0]=M12-M21; P[1]=M20-M02; P[2]=M01-M10; } break;
            }
            if (LO == 2) {
                *(float4*)Pdst     = make_float4(P[0],P[1],P[2],P[3]);
                *(float4*)(Pdst+4) = make_float4(P[4],P[5],P[6],P[7]);
                Pdst[8] = P[8];
            } else if (LO == 1) {
                *(float4*)Pdst = make_float4(P[0],P[1],P[2],0.f);
            } else {
                Pdst[0] = P[0];
            }
        }

        asm volatile("cp.async.wait_group 1;");   // W(s) landed; W(s+1) may fly
        __syncthreads();

        // ---- accumulate: half-warp h handles elem e, channels 4cl..4cl+3 ----
        const float* Pp   = Ps + e*PESTRIDE;
        const float* Wcur = Wb + (s&1)*WBUF + 4*cl;
        if (LO == 2) {
            #pragma unroll 2
            for (int b = 0; b < 64; ++b) {
                ulonglong2 q0 = *(const ulonglong2*)(Pp + b*PROW);
                ulonglong2 q1 = *(const ulonglong2*)(Pp + b*PROW + 4);
                float p8 = Pp[b*PROW + 8];
                float4 wv = *(const float4*)(Wcur + b*64);
                const float wf[4] = {wv.x, wv.y, wv.z, wv.w};
                #pragma unroll
                for (int i = 0; i < 4; ++i) {
                    ull ww = packf2(wf[i], wf[i]);
                    ffma2(a2p[i][0], ww, q0.x);
                    ffma2(a2p[i][1], ww, q0.y);
                    ffma2(a2p[i][2], ww, q1.x);
                    ffma2(a2p[i][3], ww, q1.y);
                    a2s[i] = fmaf(wf[i], p8, a2s[i]);
                }
            }
        } else if (LO == 1) {
            #pragma unroll 2
            for (int b = 0; b < 64; ++b) {
                ull p01 = *(const ull*)(Pp + b*PROW);
                float p2 = Pp[b*PROW + 2];
                float4 wv = *(const float4*)(Wcur + b*64);
                const float wf[4] = {wv.x, wv.y, wv.z, wv.w};
                #pragma unroll
                for (int i = 0; i < 4; ++i) {
                    ull ww = packf2(wf[i], wf[i]);
                    ffma2(a1p[i], ww, p01);
                    a1s[i] = fmaf(wf[i], p2, a1s[i]);
                }
            }
        } else {
            #pragma unroll 4
            for (int b = 0; b < 64; ++b) {
                float p0 = Pp[b*PROW];
                float4 wv = *(const float4*)(Wcur + b*64);
                acc0[0] = fmaf(wv.x, p0, acc0[0]);
                acc0[1] = fmaf(wv.y, p0, acc0[1]);
                acc0[2] = fmaf(wv.z, p0, acc0[2]);
                acc0[3] = fmaf(wv.w, p0, acc0[3]);
            }
        }
        __syncthreads();   // P + Wbuf free for next step

        if (++a == 64) { a = 0; ++p; }
    }

    // ---- epilogue: each lane writes its (elem, 4 channels); every slot once ----
    float* o = out + ((size_t)blk*TB + e)*FEAT;
    #pragma unroll
    for (int i = 0; i < 4; ++i) {
        const int c = 4*cl + i;
        o[c] = acc0[i];
        float t0, t1;
        unpackf2(a1p[i], t0, t1);
        o[64 + c*3 + 0] = t0; o[64 + c*3 + 1] = t1; o[64 + c*3 + 2] = a1s[i];
        float* o2 = o + 256 + c*9;
        unpackf2(a2p[i][0], t0, t1); o2[0]=t0; o2[1]=t1;
        unpackf2(a2p[i][1], t0, t1); o2[2]=t0; o2[3]=t1;
        unpackf2(a2p[i][2], t0, t1); o2[4]=t0; o2[5]=t1;
        unpackf2(a2p[i][3], t0, t1); o2[6]=t0; o2[7]=t1;
        o2[8] = a2s[i];
    }
}

extern "C" void kernel_launch(void* const* d_in, const int* in_sizes, int n_in,
                              void* d_out, int out_size)
{
    const float* x1  = (const float*)d_in[0];
    const float* x2  = (const float*)d_in[1];
    const float* wgt = (const float*)d_in[2];
    float* out = (float*)d_out;

    const int nbatch = in_sizes[0] / FEAT;     // 4096
    const int grid   = nbatch / TB;            // 512

    tp_transpose<<<NSTEPS, 256>>>(wgt);

    cudaFuncSetAttribute(tp_main, cudaFuncAttributeMaxDynamicSharedMemorySize, SMEM_BYTES);
    tp_main<<<grid, NT, SMEM_BYTES>>>(x1, x2, out);
}

// round 5
// speedup vs baseline: 1.7475x; 1.0375x over previous
#include <cuda_runtime.h>
#include <cstdint>
#include <cstddef>

#define FEAT     832            // 64 * (1+3+9)
#define NPATH    15
#define WSZ      262144         // 64*64*64 weights per path
#define NSTEPS   (NPATH*64)     // 960
#define TB       8              // batch elems per CTA
#define NT       256            // threads per CTA (8 warps; warp = 1 elem)
#define PROW     12             // floats per P row (9 used + pad, 16B aligned)
#define PESTRIDE 772            // 64*PROW + 4
#define WBUF     4096           // floats per W step buffer (64 b x 64 c)

__constant__ int c_L1[NPATH] = {0,0,0,1,1,1,1,1,1,2,2,2,2,2,2};
__constant__ int c_L2[NPATH] = {0,1,2,0,1,1,1,2,2,0,1,1,2,2,2};
__constant__ int c_LO[NPATH] = {0,1,2,1,2,0,1,1,2,2,1,2,2,0,1};

// Transposed weights: g_wt[(p*64 + a)*4096 + b*64 + c]
__device__ float g_wt[NPATH * WSZ];

typedef unsigned long long ull;

__device__ __forceinline__ void ffma2(ull &d, ull a, ull b) {
    asm("fma.rn.f32x2 %0, %1, %2, %0;" : "+l"(d) : "l"(a), "l"(b));
}
__device__ __forceinline__ ull packf2(float x, float y) {
    ull r; asm("mov.b64 %0, {%1,%2};" : "=l"(r) : "f"(x), "f"(y)); return r;
}
__device__ __forceinline__ void unpackf2(ull v, float &x, float &y) {
    asm("mov.b64 {%0,%1}, %2;" : "=f"(x), "=f"(y) : "l"(v));
}
__device__ __forceinline__ uint32_t smem_u32(const void* p) {
    uint32_t a;
    asm("{ .reg .u64 t; cvta.to.shared.u64 t, %1; cvt.u32.u64 %0, t; }" : "=r"(a) : "l"(p));
    return a;
}
__device__ __forceinline__ void cpasync16(uint32_t dst, const void* src) {
    asm volatile("cp.async.cg.shared.global [%0], [%1], 16;" :: "r"(dst), "l"(src));
}

// ---------------- transpose kernel: wgt[p][c][a*64+b] -> g_wt[(p*64+a)][b][c] ----
__global__ void __launch_bounds__(256)
tp_transpose(const float* __restrict__ wgt)
{
    __shared__ float t[64*65];
    const int pa = blockIdx.x;              // 0..959
    const int p = pa >> 6, a = pa & 63;
    const float* src = wgt + (size_t)p*WSZ + (size_t)a*64;
    float* dst = g_wt + (size_t)pa*WBUF;
    const int tid = threadIdx.x;
    const int c = tid >> 2, bq = tid & 3;   // c 0..63, 16 b's per thread
    #pragma unroll
    for (int k = 0; k < 4; ++k) {
        float4 v = *(const float4*)(src + (size_t)c*4096 + bq*16 + k*4);
        int b = bq*16 + k*4;
        t[c*65+b] = v.x; t[c*65+b+1] = v.y; t[c*65+b+2] = v.z; t[c*65+b+3] = v.w;
    }
    __syncthreads();
    const int b2 = tid >> 2, cq = tid & 3;
    #pragma unroll
    for (int k = 0; k < 4; ++k) {
        int c0 = cq*16 + k*4;
        float4 v = make_float4(t[(c0+0)*65 + b2], t[(c0+1)*65 + b2],
                               t[(c0+2)*65 + b2], t[(c0+3)*65 + b2]);
        *(float4*)(dst + b2*64 + c0) = v;
    }
}

// ---------------- main kernel --------------------------------------------------
// smem floats: As 8*832 | Bs 8*832 | W 2*4096 | P 8*772  = 27680 floats (110.7KB)
#define SMEM_FLOATS (2*TB*FEAT + 2*WBUF + TB*PESTRIDE)
#define SMEM_BYTES  (SMEM_FLOATS*4)

__global__ void __launch_bounds__(NT, 2)
tp_main(const float* __restrict__ x1, const float* __restrict__ x2,
        float* __restrict__ out)
{
    extern __shared__ float sm[];
    float* As = sm;                       // [TB][832]
    float* Bs = As + TB*FEAT;
    float* Wb = Bs + TB*FEAT;             // 2 x [64 b][64 c]
    float* Ps = Wb + 2*WBUF;              // [TB][PESTRIDE]

    const int tid = threadIdx.x;
    const int w   = tid >> 5;             // warp 0..7 == elem within tile
    const int l   = tid & 31;             // lane; owns channels 2l, 2l+1
    const int blk = blockIdx.x;

    // ---- tile load ----
    {
        const float4* g1 = (const float4*)(x1 + (size_t)blk*TB*FEAT);
        const float4* g2 = (const float4*)(x2 + (size_t)blk*TB*FEAT);
        float4* s1 = (float4*)As; float4* s2 = (float4*)Bs;
        const int nv = TB*FEAT/4;         // 1664
        for (int i = tid; i < nv; i += NT) { s1[i] = g1[i]; s2[i] = g2[i]; }
    }

    // ---- accumulators: 2 channels x {1,3,9} ----
    float acc0[2] = {0,0};
    ull   a1p[2] = {0,0};
    float a1s[2] = {0,0};
    ull   a2p[2][4] = {{0,0,0,0},{0,0,0,0}};
    float a2s[2] = {0,0};

    // ---- W copy machinery (each thread copies 64B = 4 x 16B) ----
    const uint32_t wsm0 = smem_u32(Wb) + tid*64;
    const float* wtsrc0 = g_wt + (size_t)tid*16;

    // issue copy for step 0 into buffer 0
    {
        const float* s = wtsrc0;
        #pragma unroll
        for (int k = 0; k < 4; ++k) cpasync16(wsm0 + k*16, s + k*4);
        asm volatile("cp.async.commit_group;");
    }
    __syncthreads();   // tile load visible before pair phase

    int p = 0, a = 0;
    #pragma unroll 1
    for (int s = 0; s < NSTEPS; ++s) {
        // prefetch next step's W into the other buffer
        if (s + 1 < NSTEPS) {
            const float* src = wtsrc0 + (size_t)(s+1)*WBUF;
            const uint32_t dst = wsm0 + ((s+1)&1)*(WBUF*4);
            #pragma unroll
            for (int k = 0; k < 4; ++k) cpasync16(dst + k*16, src + k*4);
        }
        asm volatile("cp.async.commit_group;");

        const int L1 = c_L1[p], L2 = c_L2[p], LO = c_LO[p];
        const int aoff = (L1==0) ? a : ((L1==1) ? (64 + a*3) : (256 + a*9));

        // ---- pair phase: 512 rows / 256 threads = 2 rows each ----
        #pragma unroll
        for (int it = 0; it < 2; ++it) {
            const int pr = tid + it*NT;               // 0..511
            const int tb = pr >> 6, b = pr & 63;
            const float* Aa = As + tb*FEAT + aoff;
            const float* Bv = Bs + tb*FEAT + ((L2==0) ? b : ((L2==1) ? (64 + b*3) : (256 + b*9)));
            float* Pdst = Ps + tb*PESTRIDE + b*PROW;
            float P[9];
            switch (p) {
            case 0:  P[0] = Aa[0]*Bv[0]; break;
            case 1:  { float v=Aa[0]; P[0]=v*Bv[0]; P[1]=v*Bv[1]; P[2]=v*Bv[2]; } break;
            case 2:  {
                       float v=Aa[0];
                       #pragma unroll
                       for (int j=0;j<9;++j) P[j]=v*Bv[j];
                     } break;
            case 3:  { float v=Bv[0]; P[0]=Aa[0]*v; P[1]=Aa[1]*v; P[2]=Aa[2]*v; } break;
            case 4:  { float u0=Aa[0],u1=Aa[1],u2=Aa[2],v0=Bv[0],v1=Bv[1],v2=Bv[2];
                       P[0]=u0*v0;P[1]=u0*v1;P[2]=u0*v2;
                       P[3]=u1*v0;P[4]=u1*v1;P[5]=u1*v2;
                       P[6]=u2*v0;P[7]=u2*v1;P[8]=u2*v2; } break;
            case 5:  P[0] = Aa[0]*Bv[0] + Aa[1]*Bv[1] + Aa[2]*Bv[2]; break;
            case 6:  { float u0=Aa[0],u1=Aa[1],u2=Aa[2],v0=Bv[0],v1=Bv[1],v2=Bv[2];
                       P[0]=u1*v2-u2*v1; P[1]=u2*v0-u0*v2; P[2]=u0*v1-u1*v0; } break;
            case 7:  { float u0=Aa[0],u1=Aa[1],u2=Aa[2];
                       P[0]=u0*Bv[0]+u1*Bv[1]+u2*Bv[2];
                       P[1]=u0*Bv[3]+u1*Bv[4]+u2*Bv[5];
                       P[2]=u0*Bv[6]+u1*Bv[7]+u2*Bv[8]; } break;
            case 8:  {
                       float u0=Aa[0],u1=Aa[1],u2=Aa[2];
                       #pragma unroll
                       for (int q=0;q<3;++q) {
                           float v0=Bv[q*3],v1=Bv[q*3+1],v2=Bv[q*3+2];
                           P[q*3+0]=u1*v2-u2*v1; P[q*3+1]=u2*v0-u0*v2; P[q*3+2]=u0*v1-u1*v0;
                       }
                     } break;
            case 9:  {
                       float v=Bv[0];
                       #pragma unroll
                       for (int j=0;j<9;++j) P[j]=Aa[j]*v;
                     } break;
            case 10: { float v0=Bv[0],v1=Bv[1],v2=Bv[2];
                       P[0]=Aa[0]*v0+Aa[1]*v1+Aa[2]*v2;
                       P[1]=Aa[3]*v0+Aa[4]*v1+Aa[5]*v2;
                       P[2]=Aa[6]*v0+Aa[7]*v1+Aa[8]*v2; } break;
            case 11: {
                       float v0=Bv[0],v1=Bv[1],v2=Bv[2];
                       #pragma unroll
                       for (int d=0;d<3;++d) {
                           float u0=Aa[d*3],u1=Aa[d*3+1],u2=Aa[d*3+2];
                           P[d*3+0]=u1*v2-u2*v1; P[d*3+1]=u2*v0-u0*v2; P[d*3+2]=u0*v1-u1*v0;
                       }
                     } break;
            case 12: {
                       #pragma unroll
                       for (int d=0;d<3;++d) {
                           float u0=Aa[d*3],u1=Aa[d*3+1],u2=Aa[d*3+2];
                           #pragma unroll
                           for (int f=0;f<3;++f)
                               P[d*3+f]=u0*Bv[f*3]+u1*Bv[f*3+1]+u2*Bv[f*3+2];
                       }
                     } break;
            case 13: {
                       float v=0.f;
                       #pragma unroll
                       for (int j=0;j<9;++j) v += Aa[j]*Bv[j];
                       P[0]=v;
                     } break;
            default: { // 14: antisymmetric part of M[d][f] = dot(A2[d,:], B2[f,:])
                       float M01 = Aa[0]*Bv[3]+Aa[1]*Bv[4]+Aa[2]*Bv[5];
                       float M02 = Aa[0]*Bv[6]+Aa[1]*Bv[7]+Aa[2]*Bv[8];
                       float M10 = Aa[3]*Bv[0]+Aa[4]*Bv[1]+Aa[5]*Bv[2];
                       float M12 = Aa[3]*Bv[6]+Aa[4]*Bv[7]+Aa[5]*Bv[8];
                       float M20 = Aa[6]*Bv[0]+Aa[7]*Bv[1]+Aa[8]*Bv[2];
                       float M21 = Aa[6]*Bv[3]+Aa[7]*Bv[4]+Aa[8]*Bv[5];
                       P[0]=M12-M21; P[1]=M20-M02; P[2]=M01-M10; } break;
            }
            if (LO == 2) {
                *(float4*)Pdst     = make_float4(P[0],P[1],P[2],P[3]);
                *(float4*)(Pdst+4) = make_float4(P[4],P[5],P[6],P[7]);
                Pdst[8] = P[8];
            } else if (LO == 1) {
                *(float4*)Pdst = make_float4(P[0],P[1],P[2],0.f);
            } else {
                Pdst[0] = P[0];
            }
        }

        asm volatile("cp.async.wait_group 1;");   // W(s) landed; W(s+1) may fly
        __syncthreads();

        // ---- accumulate: warp w handles elem w, channels 2l, 2l+1 ----
        const float* Pp   = Ps + w*PESTRIDE;
        const float* Wcur = Wb + (s&1)*WBUF;      // [b][64 c]
        if (LO == 2) {
            #pragma unroll 2
            for (int b = 0; b < 64; ++b) {
                ulonglong2 q0 = *(const ulonglong2*)(Pp + b*PROW);      // broadcast
                ulonglong2 q1 = *(const ulonglong2*)(Pp + b*PROW + 4);  // broadcast
                float p8 = Pp[b*PROW + 8];                              // broadcast
                float2 wv = *(const float2*)(Wcur + b*64 + 2*l);
                const float wf[2] = {wv.x, wv.y};
                #pragma unroll
                for (int i = 0; i < 2; ++i) {
                    ull ww = packf2(wf[i], wf[i]);
                    ffma2(a2p[i][0], ww, q0.x);
                    ffma2(a2p[i][1], ww, q0.y);
                    ffma2(a2p[i][2], ww, q1.x);
                    ffma2(a2p[i][3], ww, q1.y);
                    a2s[i] = fmaf(wf[i], p8, a2s[i]);
                }
            }
        } else if (LO == 1) {
            #pragma unroll 4
            for (int b = 0; b < 64; ++b) {
                ull p01 = *(const ull*)(Pp + b*PROW);
                float p2 = Pp[b*PROW + 2];
                float2 wv = *(const float2*)(Wcur + b*64 + 2*l);
                const float wf[2] = {wv.x, wv.y};
                #pragma unroll
                for (int i = 0; i < 2; ++i) {
                    ull ww = packf2(wf[i], wf[i]);
                    ffma2(a1p[i], ww, p01);
                    a1s[i] = fmaf(wf[i], p2, a1s[i]);
                }
            }
        } else {
            #pragma unroll 4
            for (int b = 0; b < 64; ++b) {
                float p0 = Pp[b*PROW];
                float2 wv = *(const float2*)(Wcur + b*64 + 2*l);
                acc0[0] = fmaf(wv.x, p0, acc0[0]);
                acc0[1] = fmaf(wv.y, p0, acc0[1]);
            }
        }
        __syncthreads();   // P + Wbuf free for next step

        if (++a == 64) { a = 0; ++p; }
    }

    // ---- epilogue: each lane writes its (elem, 2 channels); every slot once ----
    float* o = out + ((size_t)blk*TB + w)*FEAT;
    #pragma unroll
    for (int i = 0; i < 2; ++i) {
        const int c = 2*l + i;
        o[c] = acc0[i];
        float t0, t1;
        unpackf2(a1p[i], t0, t1);
        o[64 + c*3 + 0] = t0; o[64 + c*3 + 1] = t1; o[64 + c*3 + 2] = a1s[i];
        float* o2 = o + 256 + c*9;
        unpackf2(a2p[i][0], t0, t1); o2[0]=t0; o2[1]=t1;
        unpackf2(a2p[i][1], t0, t1); o2[2]=t0; o2[3]=t1;
        unpackf2(a2p[i][2], t0, t1); o2[4]=t0; o2[5]=t1;
        unpackf2(a2p[i][3], t0, t1); o2[6]=t0; o2[7]=t1;
        o2[8] = a2s[i];
    }
}

extern "C" void kernel_launch(void* const* d_in, const int* in_sizes, int n_in,
                              void* d_out, int out_size)
{
    const float* x1  = (const float*)d_in[0];
    const float* x2  = (const float*)d_in[1];
    const float* wgt = (const float*)d_in[2];
    float* out = (float*)d_out;

    const int nbatch = in_sizes[0] / FEAT;     // 4096
    const int grid   = nbatch / TB;            // 512

    tp_transpose<<<NSTEPS, 256>>>(wgt);

    cudaFuncSetAttribute(tp_main, cudaFuncAttributeMaxDynamicSharedMemorySize, SMEM_BYTES);
    tp_main<<<grid, NT, SMEM_BYTES>>>(x1, x2, out);
}